// round 3
// baseline (speedup 1.0000x reference)
#include <cuda_runtime.h>
#include <math.h>

// Problem constants (fixed by setup_inputs)
#define N_  4
#define A_  3
#define S_  13
#define NC  80
#define NM  32
#define G_  16
#define H_  104
#define W_  104
#define PC  (5 + NC + NM)   // 117
#define HW  (H_ * W_)       // 10816
#define NCELL (N_ * A_ * S_ * S_)  // 2028
#define NQ  10               // partial fields per cell

// SoA partials: [field][cell]. Every slot overwritten each replay -> no zeroing.
__device__ float        g_part[NQ][NCELL];
__device__ unsigned int g_count = 0;   // zero at load; last block resets to 0

__device__ __forceinline__ float bce_logits(float x, float z) {
    return fmaxf(x, 0.0f) - x * z + log1pf(expf(-fabsf(x)));
}

// field indices
// 0: noobj_bce  1: n_noobj  2: obj_bce  3: (1-giou)  4: xy_bce
// 5: wh_mse     6: cls_nll  7: seg_mean 8: n_obj     9: n_valid

__global__ void __launch_bounds__(128)
fused_kernel(const float* __restrict__ preds,
             const float* __restrict__ target,
             const float* __restrict__ anchors,
             const float* __restrict__ proto,
             const float* __restrict__ masks,
             float* __restrict__ out)
{
    const int c   = blockIdx.x;
    const int tid = threadIdx.x;

    const float* t = target + (size_t)c * 7;
    const float* p = preds  + (size_t)c * PC;

    __shared__ float tc[NM];
    __shared__ float sred[128];
    __shared__ float s_cls;
    __shared__ int   sh_y1, sh_ny, sh_x1, sh_nx, sh_area, sh_id;
    __shared__ int   sh_last;

    const float conf_t = t[4];
    const bool  obj    = (conf_t == 1.0f);

    if (!obj) {
        if (tid == 0) {
            const float nb = (conf_t == 0.0f) ? bce_logits(p[4], 0.0f) : 0.0f;
            g_part[0][c] = nb;
            g_part[1][c] = (conf_t == 0.0f) ? 1.0f : 0.0f;
            #pragma unroll
            for (int q = 2; q < NQ; q++) g_part[q][c] = 0.0f;
        }
    } else {
        // decode (n, a, i, j)
        const int n   = c / (A_ * S_ * S_);
        const int rem = c % (A_ * S_ * S_);
        const int a   = rem / (S_ * S_);
        const int ij  = rem % (S_ * S_);
        const int i   = ij / S_;
        const int j   = ij % S_;

        float v_obj = 0.f, v_giou1m = 0.f, v_xy = 0.f, v_wh = 0.f;

        // ---- warp 0 lane 0: box / giou / obj / xy / wh + region bounds ----
        if (tid == 0) {
            const float anw = anchors[a * 2 + 0];
            const float anh = anchors[a * 2 + 1];

            const float sx = 1.0f / (1.0f + expf(-p[0]));
            const float sy = 1.0f / (1.0f + expf(-p[1]));
            const float pw = expf(p[2]) * anw;
            const float ph = expf(p[3]) * anh;

            const float tx = t[0], ty = t[1], tw = t[2], th = t[3];

            const float eps = 1e-9f;
            const float b1x1 = sx - pw * 0.5f, b1y1 = sy - ph * 0.5f;
            const float b1x2 = sx + pw * 0.5f, b1y2 = sy + ph * 0.5f;
            const float b2x1 = tx - tw * 0.5f, b2y1 = ty - th * 0.5f;
            const float b2x2 = tx + tw * 0.5f, b2y2 = ty + th * 0.5f;
            const float a1 = fmaxf(b1x2 - b1x1, 0.0f) * fmaxf(b1y2 - b1y1, 0.0f) + eps;
            const float a2 = fmaxf(b2x2 - b2x1, 0.0f) * fmaxf(b2y2 - b2y1, 0.0f) + eps;
            const float iw = fmaxf(fminf(b1x2, b2x2) - fmaxf(b1x1, b2x1), 0.0f);
            const float ih = fmaxf(fminf(b1y2, b2y2) - fmaxf(b1y1, b2y1), 0.0f);
            const float inter = iw * ih + eps;
            const float uni   = a1 + a2 - inter + eps;
            const float iou   = inter / uni;
            const float cwd = fmaxf(b1x2, b2x2) - fminf(b1x1, b2x1);
            const float chd = fmaxf(b1y2, b2y2) - fminf(b1y1, b2y1);
            const float carea = cwd * chd + eps;
            const float giou  = iou - (carea - uni) / carea;

            v_giou1m = 1.0f - giou;
            v_obj    = bce_logits(p[4], conf_t * fmaxf(giou, 0.0f));
            v_xy     = bce_logits(sx, tx) + bce_logits(sy, ty);
            const float dw = p[2] - logf(1e-16f + tw / anw);
            const float dh = p[3] - logf(1e-16f + th / anh);
            v_wh     = dw * dw + dh * dh;

            // segment region bounds
            const float bx = (tx + (float)j) * ((float)W_ / (float)S_);
            const float by = (ty + (float)i) * ((float)H_ / (float)S_);
            const float bw = tw * ((float)W_ / (float)S_);
            const float bh = th * ((float)H_ / (float)S_);
            const int x1 = (int)floorf(bx - bw * 0.5f);
            const int x2 = (int)floorf(bx + bw * 0.5f);
            const int y1 = (int)floorf(by - bh * 0.5f);
            const int y2 = (int)floorf(by + bh * 0.5f);
            const int yl = max(y1, 0), yh = min(y2, H_);
            const int xl = max(x1, 0), xh = min(x2, W_);
            const int nrows = max(0, yh - yl);
            const int ncols = max(0, xh - xl);
            sh_y1 = yl; sh_ny = nrows;
            sh_x1 = xl; sh_nx = ncols;
            sh_area = nrows * ncols;
            int id = (int)t[6];
            sh_id = min(max(id, 0), G_ - 1);
        }

        // ---- warp 1: class log-softmax (shuffle-parallel over 80) ----
        if (tid >= 32 && tid < 64) {
            const int lane = tid - 32;
            float m = -3.4e38f;
            for (int k = lane; k < NC; k += 32) m = fmaxf(m, p[5 + k]);
            #pragma unroll
            for (int off = 16; off > 0; off >>= 1)
                m = fmaxf(m, __shfl_xor_sync(0xffffffffu, m, off));
            float se = 0.0f;
            for (int k = lane; k < NC; k += 32) se += expf(p[5 + k] - m);
            #pragma unroll
            for (int off = 16; off > 0; off >>= 1)
                se += __shfl_xor_sync(0xffffffffu, se, off);
            if (lane == 0) {
                const int lab = (int)t[5];
                s_cls = -(p[5 + lab] - m - logf(se));
            }
        }

        // ---- warp 2: tanh of the 32 mask coefficients ----
        if (tid >= 64 && tid < 96) tc[tid - 64] = tanhf(p[5 + NC + (tid - 64)]);

        __syncthreads();

        // ---- segment region sweep (all 128 threads) ----
        const int area = sh_area;
        float acc = 0.0f;
        if (area > 0) {
            const float* __restrict__ pr = proto + (size_t)n * NM * HW;
            const float* __restrict__ tm = masks + ((size_t)n * G_ + sh_id) * HW;
            const int npix = sh_ny * sh_nx;
            const int nx   = sh_nx;
            for (int pix = tid; pix < npix; pix += 128) {
                const int r  = pix / nx;
                const int cc = pix - r * nx;
                const int off = (sh_y1 + r) * W_ + (sh_x1 + cc);
                float dot = 0.0f;
                #pragma unroll
                for (int m = 0; m < NM; m++)
                    dot = fmaf(tc[m], pr[m * HW + off], dot);
                acc += bce_logits(dot, tm[off]);
            }
        }
        sred[tid] = acc;
        __syncthreads();
        #pragma unroll
        for (int s = 64; s > 0; s >>= 1) {
            if (tid < s) sred[tid] += sred[tid + s];
            __syncthreads();
        }

        if (tid == 0) {
            g_part[0][c] = 0.0f;
            g_part[1][c] = 0.0f;
            g_part[2][c] = v_obj;
            g_part[3][c] = v_giou1m;
            g_part[4][c] = v_xy;
            g_part[5][c] = v_wh;
            g_part[6][c] = s_cls;
            g_part[7][c] = (area > 0) ? sred[0] / (float)area : 0.0f;
            g_part[8][c] = 1.0f;
            g_part[9][c] = (area > 0) ? 1.0f : 0.0f;
        }
    }

    // ---- ticket: ONLY tid 0 fences (release) + arrives ----
    if (tid == 0) {
        __threadfence();                       // release g_part writes
        const unsigned prev = atomicAdd(&g_count, 1u);
        sh_last = (prev == (unsigned)(gridDim.x - 1)) ? 1 : 0;
        if (sh_last) __threadfence();          // acquire before reading g_part
    }
    __syncthreads();
    if (!sh_last) return;

    // ---- last-block reduction (reads bypass L1 via __ldcg) ----
    __shared__ double dred[128];
    double fin[NQ];
    #pragma unroll
    for (int q = 0; q < NQ; q++) {
        double a = 0.0;
        for (int cc = tid; cc < NCELL; cc += 128)
            a += (double)__ldcg(&g_part[q][cc]);
        dred[tid] = a;
        __syncthreads();
        #pragma unroll
        for (int s = 64; s > 0; s >>= 1) {
            if (tid < s) dred[tid] += dred[tid + s];
            __syncthreads();
        }
        fin[q] = dred[0];
        __syncthreads();
    }

    if (tid == 0) {
        const double n_noobj = fin[1], n_obj = fin[8], n_valid = fin[9];
        const double noobj_loss = fin[0] / n_noobj;
        const double obj_loss   = fin[2] / n_obj;
        const double box_loss   = fin[4] / (n_obj * 2.0)
                                + fin[5] / (n_obj * 2.0)
                                + fin[3] / n_obj;
        const double class_loss = fin[6] / n_obj;
        const double seg_loss   = fin[7] / (n_valid + 1e-9);

        const double box_l   = 8.0  * box_loss;
        const double obj_l   = 2.0  * obj_loss;
        const double noobj_l = 4.0  * noobj_loss;
        const double cls_l   = 1.0  * class_loss;
        const double seg_l   = 10.0 * seg_loss;

        out[0] = (float)box_l;
        out[1] = (float)obj_l;
        out[2] = (float)noobj_l;
        out[3] = (float)cls_l;
        out[4] = (float)seg_l;
        out[5] = (float)(box_l + obj_l + noobj_l + cls_l + seg_l);

        g_count = 0;   // reset for next graph replay
    }
}

extern "C" void kernel_launch(void* const* d_in, const int* in_sizes, int n_in,
                              void* d_out, int out_size)
{
    const float* preds   = (const float*)d_in[0];
    const float* target  = (const float*)d_in[1];
    const float* anchors = (const float*)d_in[2];
    const float* proto   = (const float*)d_in[3];
    const float* masks   = (const float*)d_in[4];
    float* out = (float*)d_out;

    fused_kernel<<<NCELL, 128>>>(preds, target, anchors, proto, masks, out);
}

// round 4
// speedup vs baseline: 1.2869x; 1.2869x over previous
#include <cuda_runtime.h>
#include <math.h>

// Problem constants (fixed by setup_inputs)
#define N_  4
#define A_  3
#define S_  13
#define NC  80
#define NM  32
#define G_  16
#define H_  104
#define W_  104
#define PC  (5 + NC + NM)   // 117
#define HW  (H_ * W_)       // 10816
#define NCELL (N_ * A_ * S_ * S_)  // 2028
#define NQ  10               // partial fields per cell

// SoA partials: [field][cell]. Every slot overwritten each replay -> no zeroing.
__device__ float        g_part[NQ][NCELL];
__device__ unsigned int g_count = 0;   // zero at load; last block resets to 0

__device__ __forceinline__ float bce_logits(float x, float z) {
    return fmaxf(x, 0.0f) - x * z + log1pf(expf(-fabsf(x)));
}

// Release/acq_rel ticket: ATOMG.STRONG.GPU — orders prior STGs into L2
// WITHOUT emitting MEMBAR.GPU/CCTL.IVALL (no L1 flush).
__device__ __forceinline__ unsigned ticket_acq_rel(unsigned int* p) {
    unsigned prev;
    asm volatile("atom.acq_rel.gpu.global.add.u32 %0, [%1], %2;"
                 : "=r"(prev) : "l"(p), "r"(1u) : "memory");
    return prev;
}

// field indices
// 0: noobj_bce  1: n_noobj  2: obj_bce  3: (1-giou)  4: xy_bce
// 5: wh_mse     6: cls_nll  7: seg_mean 8: n_obj     9: n_valid

__global__ void __launch_bounds__(128)
fused_kernel(const float* __restrict__ preds,
             const float* __restrict__ target,
             const float* __restrict__ anchors,
             const float* __restrict__ proto,
             const float* __restrict__ masks,
             float* __restrict__ out)
{
    const int c   = blockIdx.x;
    const int tid = threadIdx.x;

    const float* t = target + (size_t)c * 7;
    const float* p = preds  + (size_t)c * PC;

    __shared__ float tc[NM];
    __shared__ float sred[128];
    __shared__ float s_cls;
    __shared__ int   sh_y1, sh_ny, sh_x1, sh_nx, sh_area, sh_id;
    __shared__ int   sh_last;

    const float conf_t = t[4];
    const bool  obj    = (conf_t == 1.0f);

    if (!obj) {
        if (tid == 0) {
            const float nb = (conf_t == 0.0f) ? bce_logits(p[4], 0.0f) : 0.0f;
            g_part[0][c] = nb;
            g_part[1][c] = (conf_t == 0.0f) ? 1.0f : 0.0f;
            #pragma unroll
            for (int q = 2; q < NQ; q++) g_part[q][c] = 0.0f;
        }
    } else {
        // decode (n, a, i, j)
        const int n   = c / (A_ * S_ * S_);
        const int rem = c % (A_ * S_ * S_);
        const int a   = rem / (S_ * S_);
        const int ij  = rem % (S_ * S_);
        const int i   = ij / S_;
        const int j   = ij % S_;

        float v_obj = 0.f, v_giou1m = 0.f, v_xy = 0.f, v_wh = 0.f;

        // ---- warp 0 lane 0: box / giou / obj / xy / wh + region bounds ----
        if (tid == 0) {
            const float anw = anchors[a * 2 + 0];
            const float anh = anchors[a * 2 + 1];

            const float sx = 1.0f / (1.0f + expf(-p[0]));
            const float sy = 1.0f / (1.0f + expf(-p[1]));
            const float pw = expf(p[2]) * anw;
            const float ph = expf(p[3]) * anh;

            const float tx = t[0], ty = t[1], tw = t[2], th = t[3];

            const float eps = 1e-9f;
            const float b1x1 = sx - pw * 0.5f, b1y1 = sy - ph * 0.5f;
            const float b1x2 = sx + pw * 0.5f, b1y2 = sy + ph * 0.5f;
            const float b2x1 = tx - tw * 0.5f, b2y1 = ty - th * 0.5f;
            const float b2x2 = tx + tw * 0.5f, b2y2 = ty + th * 0.5f;
            const float a1 = fmaxf(b1x2 - b1x1, 0.0f) * fmaxf(b1y2 - b1y1, 0.0f) + eps;
            const float a2 = fmaxf(b2x2 - b2x1, 0.0f) * fmaxf(b2y2 - b2y1, 0.0f) + eps;
            const float iw = fmaxf(fminf(b1x2, b2x2) - fmaxf(b1x1, b2x1), 0.0f);
            const float ih = fmaxf(fminf(b1y2, b2y2) - fmaxf(b1y1, b2y1), 0.0f);
            const float inter = iw * ih + eps;
            const float uni   = a1 + a2 - inter + eps;
            const float iou   = inter / uni;
            const float cwd = fmaxf(b1x2, b2x2) - fminf(b1x1, b2x1);
            const float chd = fmaxf(b1y2, b2y2) - fminf(b1y1, b2y1);
            const float carea = cwd * chd + eps;
            const float giou  = iou - (carea - uni) / carea;

            v_giou1m = 1.0f - giou;
            v_obj    = bce_logits(p[4], conf_t * fmaxf(giou, 0.0f));
            v_xy     = bce_logits(sx, tx) + bce_logits(sy, ty);
            const float dw = p[2] - logf(1e-16f + tw / anw);
            const float dh = p[3] - logf(1e-16f + th / anh);
            v_wh     = dw * dw + dh * dh;

            // segment region bounds
            const float bx = (tx + (float)j) * ((float)W_ / (float)S_);
            const float by = (ty + (float)i) * ((float)H_ / (float)S_);
            const float bw = tw * ((float)W_ / (float)S_);
            const float bh = th * ((float)H_ / (float)S_);
            const int x1 = (int)floorf(bx - bw * 0.5f);
            const int x2 = (int)floorf(bx + bw * 0.5f);
            const int y1 = (int)floorf(by - bh * 0.5f);
            const int y2 = (int)floorf(by + bh * 0.5f);
            const int yl = max(y1, 0), yh = min(y2, H_);
            const int xl = max(x1, 0), xh = min(x2, W_);
            const int nrows = max(0, yh - yl);
            const int ncols = max(0, xh - xl);
            sh_y1 = yl; sh_ny = nrows;
            sh_x1 = xl; sh_nx = ncols;
            sh_area = nrows * ncols;
            int id = (int)t[6];
            sh_id = min(max(id, 0), G_ - 1);
        }

        // ---- warp 1: class log-softmax (shuffle-parallel over 80) ----
        if (tid >= 32 && tid < 64) {
            const int lane = tid - 32;
            float m = -3.4e38f;
            for (int k = lane; k < NC; k += 32) m = fmaxf(m, p[5 + k]);
            #pragma unroll
            for (int off = 16; off > 0; off >>= 1)
                m = fmaxf(m, __shfl_xor_sync(0xffffffffu, m, off));
            float se = 0.0f;
            for (int k = lane; k < NC; k += 32) se += expf(p[5 + k] - m);
            #pragma unroll
            for (int off = 16; off > 0; off >>= 1)
                se += __shfl_xor_sync(0xffffffffu, se, off);
            if (lane == 0) {
                const int lab = (int)t[5];
                s_cls = -(p[5 + lab] - m - logf(se));
            }
        }

        // ---- warp 2: tanh of the 32 mask coefficients ----
        if (tid >= 64 && tid < 96) tc[tid - 64] = tanhf(p[5 + NC + (tid - 64)]);

        __syncthreads();

        // ---- segment region sweep (all 128 threads) ----
        const int area = sh_area;
        float acc = 0.0f;
        if (area > 0) {
            const float* __restrict__ pr = proto + (size_t)n * NM * HW;
            const float* __restrict__ tm = masks + ((size_t)n * G_ + sh_id) * HW;
            const int npix = sh_ny * sh_nx;
            const int nx   = sh_nx;
            for (int pix = tid; pix < npix; pix += 128) {
                const int r  = pix / nx;
                const int cc = pix - r * nx;
                const int off = (sh_y1 + r) * W_ + (sh_x1 + cc);
                float dot = 0.0f;
                #pragma unroll
                for (int m = 0; m < NM; m++)
                    dot = fmaf(tc[m], pr[m * HW + off], dot);
                acc += bce_logits(dot, tm[off]);
            }
        }
        sred[tid] = acc;
        __syncthreads();
        #pragma unroll
        for (int s = 64; s > 0; s >>= 1) {
            if (tid < s) sred[tid] += sred[tid + s];
            __syncthreads();
        }

        if (tid == 0) {
            g_part[0][c] = 0.0f;
            g_part[1][c] = 0.0f;
            g_part[2][c] = v_obj;
            g_part[3][c] = v_giou1m;
            g_part[4][c] = v_xy;
            g_part[5][c] = v_wh;
            g_part[6][c] = s_cls;
            g_part[7][c] = (area > 0) ? sred[0] / (float)area : 0.0f;
            g_part[8][c] = 1.0f;
            g_part[9][c] = (area > 0) ? 1.0f : 0.0f;
        }
    }

    // ---- ticket: release-ordered atomic, NO membar / NO L1 flush ----
    if (tid == 0) {
        const unsigned prev = ticket_acq_rel(&g_count);
        sh_last = (prev == (unsigned)(gridDim.x - 1)) ? 1 : 0;
    }
    __syncthreads();
    if (!sh_last) return;

    // ---- last-block reduction: one pass, all 10 fields, L2-direct loads ----
    __shared__ double swq[4][NQ];
    double a0=0,a1=0,a2=0,a3=0,a4=0,a5=0,a6=0,a7=0,a8=0,a9=0;
    for (int cc = tid; cc < NCELL; cc += 128) {
        a0 += (double)__ldcg(&g_part[0][cc]);
        a1 += (double)__ldcg(&g_part[1][cc]);
        a2 += (double)__ldcg(&g_part[2][cc]);
        a3 += (double)__ldcg(&g_part[3][cc]);
        a4 += (double)__ldcg(&g_part[4][cc]);
        a5 += (double)__ldcg(&g_part[5][cc]);
        a6 += (double)__ldcg(&g_part[6][cc]);
        a7 += (double)__ldcg(&g_part[7][cc]);
        a8 += (double)__ldcg(&g_part[8][cc]);
        a9 += (double)__ldcg(&g_part[9][cc]);
    }
    #pragma unroll
    for (int off = 16; off > 0; off >>= 1) {
        a0 += __shfl_xor_sync(0xffffffffu, a0, off);
        a1 += __shfl_xor_sync(0xffffffffu, a1, off);
        a2 += __shfl_xor_sync(0xffffffffu, a2, off);
        a3 += __shfl_xor_sync(0xffffffffu, a3, off);
        a4 += __shfl_xor_sync(0xffffffffu, a4, off);
        a5 += __shfl_xor_sync(0xffffffffu, a5, off);
        a6 += __shfl_xor_sync(0xffffffffu, a6, off);
        a7 += __shfl_xor_sync(0xffffffffu, a7, off);
        a8 += __shfl_xor_sync(0xffffffffu, a8, off);
        a9 += __shfl_xor_sync(0xffffffffu, a9, off);
    }
    const int warp = tid >> 5;
    if ((tid & 31) == 0) {
        swq[warp][0]=a0; swq[warp][1]=a1; swq[warp][2]=a2; swq[warp][3]=a3;
        swq[warp][4]=a4; swq[warp][5]=a5; swq[warp][6]=a6; swq[warp][7]=a7;
        swq[warp][8]=a8; swq[warp][9]=a9;
    }
    __syncthreads();

    if (tid == 0) {
        double fin[NQ];
        #pragma unroll
        for (int q = 0; q < NQ; q++)
            fin[q] = swq[0][q] + swq[1][q] + swq[2][q] + swq[3][q];

        const double n_noobj = fin[1], n_obj = fin[8], n_valid = fin[9];
        const double noobj_loss = fin[0] / n_noobj;
        const double obj_loss   = fin[2] / n_obj;
        const double box_loss   = fin[4] / (n_obj * 2.0)
                                + fin[5] / (n_obj * 2.0)
                                + fin[3] / n_obj;
        const double class_loss = fin[6] / n_obj;
        const double seg_loss   = fin[7] / (n_valid + 1e-9);

        const double box_l   = 8.0  * box_loss;
        const double obj_l   = 2.0  * obj_loss;
        const double noobj_l = 4.0  * noobj_loss;
        const double cls_l   = 1.0  * class_loss;
        const double seg_l   = 10.0 * seg_loss;

        out[0] = (float)box_l;
        out[1] = (float)obj_l;
        out[2] = (float)noobj_l;
        out[3] = (float)cls_l;
        out[4] = (float)seg_l;
        out[5] = (float)(box_l + obj_l + noobj_l + cls_l + seg_l);

        g_count = 0;   // reset for next graph replay
    }
}

extern "C" void kernel_launch(void* const* d_in, const int* in_sizes, int n_in,
                              void* d_out, int out_size)
{
    const float* preds   = (const float*)d_in[0];
    const float* target  = (const float*)d_in[1];
    const float* anchors = (const float*)d_in[2];
    const float* proto   = (const float*)d_in[3];
    const float* masks   = (const float*)d_in[4];
    float* out = (float*)d_out;

    fused_kernel<<<NCELL, 128>>>(preds, target, anchors, proto, masks, out);
}

// round 5
// speedup vs baseline: 1.5537x; 1.2074x over previous
#include <cuda_runtime.h>
#include <math.h>

// Problem constants (fixed by setup_inputs)
#define N_  4
#define A_  3
#define S_  13
#define NC  80
#define NM  32
#define G_  16
#define H_  104
#define W_  104
#define PC  (5 + NC + NM)   // 117
#define HW  (H_ * W_)       // 10816
#define NCELL (N_ * A_ * S_ * S_)  // 2028
#define WPB   16             // warps per block
#define NBLK  ((NCELL + WPB - 1) / WPB)   // 127

struct Acc {
    double noobj_sum;
    double obj_sum;
    double giou1m_sum;
    double xy_sum;
    double wh_sum;
    double cls_sum;
    double seg_sum;
    double n_obj;
    double n_noobj;
    double n_valid;
};

// Static-init zero; finalize_kernel resets to zero after every use, so every
// graph replay (and the first correctness call) starts from zero. Deterministic.
__device__ Acc g_acc;

__device__ __forceinline__ float bce_logits(float x, float z) {
    return fmaxf(x, 0.0f) - x * z + log1pf(expf(-fabsf(x)));
}

__global__ void __launch_bounds__(32 * WPB)
cell_kernel(const float* __restrict__ preds,
            const float* __restrict__ target,
            const float* __restrict__ anchors,
            const float* __restrict__ proto,
            const float* __restrict__ masks)
{
    const int wib  = threadIdx.x >> 5;          // warp in block
    const int lane = threadIdx.x & 31;
    const int c    = blockIdx.x * WPB + wib;    // one cell per warp
    if (c >= NCELL) return;

    const float* t = target + (size_t)c * 7;
    const float* p = preds  + (size_t)c * PC;

    const float conf_t = t[4];                  // broadcast load (uniform in warp)

    if (conf_t != 1.0f) {
        if (lane == 0 && conf_t == 0.0f) {
            atomicAdd(&g_acc.noobj_sum, (double)bce_logits(p[4], 0.0f));
            atomicAdd(&g_acc.n_noobj, 1.0);
        }
        return;
    }

    // ---------------- obj cell ----------------
    __shared__ float tc_sh[WPB][NM];

    // decode (n, a, i, j)
    const int n   = c / (A_ * S_ * S_);
    const int rem = c % (A_ * S_ * S_);
    const int a   = rem / (S_ * S_);
    const int ij  = rem % (S_ * S_);
    const int i   = ij / S_;
    const int j   = ij % S_;

    const float tx = t[0], ty = t[1], tw = t[2], th = t[3];

    // tanh coefficients: one per lane
    tc_sh[wib][lane] = tanhf(p[5 + NC + lane]);

    // warp-parallel log-softmax over NC=80
    float mx = -3.4e38f;
    for (int k = lane; k < NC; k += 32) mx = fmaxf(mx, p[5 + k]);
    #pragma unroll
    for (int off = 16; off > 0; off >>= 1)
        mx = fmaxf(mx, __shfl_xor_sync(0xffffffffu, mx, off));
    float se = 0.0f;
    for (int k = lane; k < NC; k += 32) se += expf(p[5 + k] - mx);
    #pragma unroll
    for (int off = 16; off > 0; off >>= 1)
        se += __shfl_xor_sync(0xffffffffu, se, off);

    // region bounds (uniform arithmetic on all lanes — cheap, no divergence)
    const float bx = (tx + (float)j) * ((float)W_ / (float)S_);
    const float by = (ty + (float)i) * ((float)H_ / (float)S_);
    const float bw = tw * ((float)W_ / (float)S_);
    const float bh = th * ((float)H_ / (float)S_);
    const int x1 = (int)floorf(bx - bw * 0.5f);
    const int x2 = (int)floorf(bx + bw * 0.5f);
    const int y1 = (int)floorf(by - bh * 0.5f);
    const int y2 = (int)floorf(by + bh * 0.5f);
    const int yl = max(y1, 0), yh = min(y2, H_);
    const int xl = max(x1, 0), xh = min(x2, W_);
    const int ny = max(0, yh - yl);
    const int nx = max(0, xh - xl);
    const int area = ny * nx;

    int id = (int)t[6];
    id = min(max(id, 0), G_ - 1);

    __syncwarp();

    // ---- region sweep: 32 lanes stride over pixels ----
    float acc = 0.0f;
    if (area > 0) {
        const float* __restrict__ pr = proto + (size_t)n * NM * HW;
        const float* __restrict__ tm = masks + ((size_t)n * G_ + id) * HW;
        const float* __restrict__ tcw = tc_sh[wib];
        const int npix = area;
        for (int pix = lane; pix < npix; pix += 32) {
            const int r  = pix / nx;
            const int cc = pix - r * nx;
            const int off = (yl + r) * W_ + (xl + cc);
            float dot = 0.0f;
            #pragma unroll
            for (int m = 0; m < NM; m++)
                dot = fmaf(tcw[m], pr[m * HW + off], dot);
            acc += bce_logits(dot, tm[off]);
        }
    }
    #pragma unroll
    for (int off = 16; off > 0; off >>= 1)
        acc += __shfl_xor_sync(0xffffffffu, acc, off);

    // ---- lane 0: scalar losses + atomics ----
    if (lane == 0) {
        const float anw = anchors[a * 2 + 0];
        const float anh = anchors[a * 2 + 1];

        const float sx = 1.0f / (1.0f + expf(-p[0]));
        const float sy = 1.0f / (1.0f + expf(-p[1]));
        const float pw = expf(p[2]) * anw;
        const float ph = expf(p[3]) * anh;

        const float eps = 1e-9f;
        const float b1x1 = sx - pw * 0.5f, b1y1 = sy - ph * 0.5f;
        const float b1x2 = sx + pw * 0.5f, b1y2 = sy + ph * 0.5f;
        const float b2x1 = tx - tw * 0.5f, b2y1 = ty - th * 0.5f;
        const float b2x2 = tx + tw * 0.5f, b2y2 = ty + th * 0.5f;
        const float a1 = fmaxf(b1x2 - b1x1, 0.0f) * fmaxf(b1y2 - b1y1, 0.0f) + eps;
        const float a2 = fmaxf(b2x2 - b2x1, 0.0f) * fmaxf(b2y2 - b2y1, 0.0f) + eps;
        const float iw = fmaxf(fminf(b1x2, b2x2) - fmaxf(b1x1, b2x1), 0.0f);
        const float ih = fmaxf(fminf(b1y2, b2y2) - fmaxf(b1y1, b2y1), 0.0f);
        const float inter = iw * ih + eps;
        const float uni   = a1 + a2 - inter + eps;
        const float iou   = inter / uni;
        const float cwd = fmaxf(b1x2, b2x2) - fminf(b1x1, b2x1);
        const float chd = fmaxf(b1y2, b2y2) - fminf(b1y1, b2y1);
        const float carea = cwd * chd + eps;
        const float giou  = iou - (carea - uni) / carea;

        atomicAdd(&g_acc.n_obj, 1.0);
        atomicAdd(&g_acc.giou1m_sum, (double)(1.0f - giou));
        atomicAdd(&g_acc.obj_sum, (double)bce_logits(p[4], conf_t * fmaxf(giou, 0.0f)));
        atomicAdd(&g_acc.xy_sum, (double)(bce_logits(sx, tx) + bce_logits(sy, ty)));
        const float dw = p[2] - logf(1e-16f + tw / anw);
        const float dh = p[3] - logf(1e-16f + th / anh);
        atomicAdd(&g_acc.wh_sum, (double)(dw * dw + dh * dh));

        const int lab = (int)t[5];
        atomicAdd(&g_acc.cls_sum, (double)(-(p[5 + lab] - mx - logf(se))));

        if (area > 0) {
            atomicAdd(&g_acc.seg_sum, (double)(acc / (float)area));
            atomicAdd(&g_acc.n_valid, 1.0);
        }
    }
}

__global__ void finalize_kernel(float* __restrict__ out) {
    if (threadIdx.x != 0) return;
    const Acc acc = g_acc;
    const double noobj_loss = acc.noobj_sum / acc.n_noobj;
    const double obj_loss   = acc.obj_sum   / acc.n_obj;
    const double box_loss   = acc.xy_sum / (acc.n_obj * 2.0)
                            + acc.wh_sum / (acc.n_obj * 2.0)
                            + acc.giou1m_sum / acc.n_obj;
    const double class_loss = acc.cls_sum / acc.n_obj;
    const double seg_loss   = acc.seg_sum / (acc.n_valid + 1e-9);

    const double box_l   = 8.0  * box_loss;
    const double obj_l   = 2.0  * obj_loss;
    const double noobj_l = 4.0  * noobj_loss;
    const double cls_l   = 1.0  * class_loss;
    const double seg_l   = 10.0 * seg_loss;

    out[0] = (float)box_l;
    out[1] = (float)obj_l;
    out[2] = (float)noobj_l;
    out[3] = (float)cls_l;
    out[4] = (float)seg_l;
    out[5] = (float)(box_l + obj_l + noobj_l + cls_l + seg_l);

    // reset accumulators for the next replay (deterministic zero start)
    g_acc.noobj_sum = 0.0; g_acc.obj_sum = 0.0; g_acc.giou1m_sum = 0.0;
    g_acc.xy_sum = 0.0;    g_acc.wh_sum = 0.0; g_acc.cls_sum = 0.0;
    g_acc.seg_sum = 0.0;   g_acc.n_obj = 0.0;  g_acc.n_noobj = 0.0;
    g_acc.n_valid = 0.0;
}

extern "C" void kernel_launch(void* const* d_in, const int* in_sizes, int n_in,
                              void* d_out, int out_size)
{
    const float* preds   = (const float*)d_in[0];
    const float* target  = (const float*)d_in[1];
    const float* anchors = (const float*)d_in[2];
    const float* proto   = (const float*)d_in[3];
    const float* masks   = (const float*)d_in[4];
    float* out = (float*)d_out;

    cell_kernel<<<NBLK, 32 * WPB>>>(preds, target, anchors, proto, masks);
    finalize_kernel<<<1, 32>>>(out);
}

// round 6
// speedup vs baseline: 2.7154x; 1.7476x over previous
#include <cuda_runtime.h>
#include <math.h>

// Problem constants (fixed by setup_inputs)
#define N_  4
#define A_  3
#define S_  13
#define NC  80
#define NM  32
#define G_  16
#define H_  104
#define W_  104
#define PC  (5 + NC + NM)   // 117
#define HW  (H_ * W_)       // 10816
#define NCELL (N_ * A_ * S_ * S_)  // 2028
#define TPB 256

struct Acc {
    double obj_sum;
    double giou1m_sum;
    double xy_sum;
    double wh_sum;
    double cls_sum;
    double seg_sum;
    double n_obj;
    double n_valid;
};

// Static-init zero; finalize_kernel resets after every use -> every replay
// (and the first correctness call) starts from zero. Deterministic.
__device__ Acc g_acc;

__device__ __forceinline__ float bce_logits(float x, float z) {
    return fmaxf(x, 0.0f) - x * z + log1pf(expf(-fabsf(x)));
}

__global__ void __launch_bounds__(TPB)
cell_kernel(const float* __restrict__ preds,
            const float* __restrict__ target,
            const float* __restrict__ anchors,
            const float* __restrict__ proto,
            const float* __restrict__ masks)
{
    const int c   = blockIdx.x;
    const int tid = threadIdx.x;

    const float* t = target + (size_t)c * 7;
    const float* p = preds  + (size_t)c * PC;

    // obj check: uniform broadcast load; non-obj blocks exit immediately
    if (t[4] != 1.0f) return;

    __shared__ float tc[NM];
    __shared__ float sred[TPB];
    __shared__ float s_cls;
    __shared__ int   sh_y1, sh_ny, sh_x1, sh_nx, sh_area, sh_id;

    // decode (n, a, i, j)
    const int n   = c / (A_ * S_ * S_);
    const int rem = c % (A_ * S_ * S_);
    const int a   = rem / (S_ * S_);
    const int ij  = rem % (S_ * S_);
    const int i   = ij / S_;
    const int j   = ij % S_;

    float v_obj = 0.f, v_giou1m = 0.f, v_xy = 0.f, v_wh = 0.f;

    // ---- warp 0 lane 0: box / giou / obj / xy / wh + region bounds ----
    if (tid == 0) {
        const float anw = anchors[a * 2 + 0];
        const float anh = anchors[a * 2 + 1];

        const float sx = 1.0f / (1.0f + expf(-p[0]));
        const float sy = 1.0f / (1.0f + expf(-p[1]));
        const float pw = expf(p[2]) * anw;
        const float ph = expf(p[3]) * anh;

        const float tx = t[0], ty = t[1], tw = t[2], th = t[3];

        const float eps = 1e-9f;
        const float b1x1 = sx - pw * 0.5f, b1y1 = sy - ph * 0.5f;
        const float b1x2 = sx + pw * 0.5f, b1y2 = sy + ph * 0.5f;
        const float b2x1 = tx - tw * 0.5f, b2y1 = ty - th * 0.5f;
        const float b2x2 = tx + tw * 0.5f, b2y2 = ty + th * 0.5f;
        const float a1 = fmaxf(b1x2 - b1x1, 0.0f) * fmaxf(b1y2 - b1y1, 0.0f) + eps;
        const float a2 = fmaxf(b2x2 - b2x1, 0.0f) * fmaxf(b2y2 - b2y1, 0.0f) + eps;
        const float iw = fmaxf(fminf(b1x2, b2x2) - fmaxf(b1x1, b2x1), 0.0f);
        const float ih = fmaxf(fminf(b1y2, b2y2) - fmaxf(b1y1, b2y1), 0.0f);
        const float inter = iw * ih + eps;
        const float uni   = a1 + a2 - inter + eps;
        const float iou   = inter / uni;
        const float cwd = fmaxf(b1x2, b2x2) - fminf(b1x1, b2x1);
        const float chd = fmaxf(b1y2, b2y2) - fminf(b1y1, b2y1);
        const float carea = cwd * chd + eps;
        const float giou  = iou - (carea - uni) / carea;

        v_giou1m = 1.0f - giou;
        v_obj    = bce_logits(p[4], fmaxf(giou, 0.0f));     // conf_t == 1
        v_xy     = bce_logits(sx, tx) + bce_logits(sy, ty);
        const float dw = p[2] - logf(1e-16f + tw / anw);
        const float dh = p[3] - logf(1e-16f + th / anh);
        v_wh     = dw * dw + dh * dh;

        // segment region bounds
        const float bx = (tx + (float)j) * ((float)W_ / (float)S_);
        const float by = (ty + (float)i) * ((float)H_ / (float)S_);
        const float bw = tw * ((float)W_ / (float)S_);
        const float bh = th * ((float)H_ / (float)S_);
        const int x1 = (int)floorf(bx - bw * 0.5f);
        const int x2 = (int)floorf(bx + bw * 0.5f);
        const int y1 = (int)floorf(by - bh * 0.5f);
        const int y2 = (int)floorf(by + bh * 0.5f);
        const int yl = max(y1, 0), yh = min(y2, H_);
        const int xl = max(x1, 0), xh = min(x2, W_);
        const int nrows = max(0, yh - yl);
        const int ncols = max(0, xh - xl);
        sh_y1 = yl; sh_ny = nrows;
        sh_x1 = xl; sh_nx = ncols;
        sh_area = nrows * ncols;
        int id = (int)t[6];
        sh_id = min(max(id, 0), G_ - 1);
    }

    // ---- warp 1: class log-softmax (shuffle-parallel over 80) ----
    if (tid >= 32 && tid < 64) {
        const int lane = tid - 32;
        float m = -3.4e38f;
        for (int k = lane; k < NC; k += 32) m = fmaxf(m, p[5 + k]);
        #pragma unroll
        for (int off = 16; off > 0; off >>= 1)
            m = fmaxf(m, __shfl_xor_sync(0xffffffffu, m, off));
        float se = 0.0f;
        for (int k = lane; k < NC; k += 32) se += expf(p[5 + k] - m);
        #pragma unroll
        for (int off = 16; off > 0; off >>= 1)
            se += __shfl_xor_sync(0xffffffffu, se, off);
        if (lane == 0) {
            const int lab = (int)t[5];
            s_cls = -(p[5 + lab] - m - logf(se));
        }
    }

    // ---- warp 2: tanh of the 32 mask coefficients ----
    if (tid >= 64 && tid < 96) tc[tid - 64] = tanhf(p[5 + NC + (tid - 64)]);

    __syncthreads();

    // ---- segment region sweep (all 256 threads) ----
    const int area = sh_area;
    float acc = 0.0f;
    if (area > 0) {
        const float* __restrict__ pr = proto + (size_t)n * NM * HW;
        const float* __restrict__ tm = masks + ((size_t)n * G_ + sh_id) * HW;
        const int npix = area;
        const int nx   = sh_nx;
        for (int pix = tid; pix < npix; pix += TPB) {
            const int r  = pix / nx;
            const int cc = pix - r * nx;
            const int off = (sh_y1 + r) * W_ + (sh_x1 + cc);
            float dot = 0.0f;
            #pragma unroll
            for (int m = 0; m < NM; m++)
                dot = fmaf(tc[m], pr[m * HW + off], dot);
            acc += bce_logits(dot, tm[off]);
        }
    }
    // warp reduce then cross-warp reduce
    #pragma unroll
    for (int off = 16; off > 0; off >>= 1)
        acc += __shfl_xor_sync(0xffffffffu, acc, off);
    if ((tid & 31) == 0) sred[tid >> 5] = acc;
    __syncthreads();
    if (tid == 0) {
        float rs = 0.0f;
        #pragma unroll
        for (int w = 0; w < TPB / 32; w++) rs += sred[w];

        atomicAdd(&g_acc.n_obj, 1.0);
        atomicAdd(&g_acc.giou1m_sum, (double)v_giou1m);
        atomicAdd(&g_acc.obj_sum, (double)v_obj);
        atomicAdd(&g_acc.xy_sum, (double)v_xy);
        atomicAdd(&g_acc.wh_sum, (double)v_wh);
        atomicAdd(&g_acc.cls_sum, (double)s_cls);
        if (area > 0) {
            atomicAdd(&g_acc.seg_sum, (double)(rs / (float)area));
            atomicAdd(&g_acc.n_valid, 1.0);
        }
    }
}

__global__ void __launch_bounds__(TPB)
finalize_kernel(const float* __restrict__ preds,
                const float* __restrict__ target,
                float* __restrict__ out)
{
    const int tid = threadIdx.x;

    // noobj BCE reduction over all cells
    float nb = 0.0f;
    float nn = 0.0f;
    for (int c = tid; c < NCELL; c += TPB) {
        const float conf_t = target[(size_t)c * 7 + 4];
        if (conf_t == 0.0f) {
            nb += bce_logits(preds[(size_t)c * PC + 4], 0.0f);
            nn += 1.0f;
        }
    }
    __shared__ double snb[TPB / 32], snn[TPB / 32];
    // widen to double per-thread then warp reduce
    double dnb = (double)nb, dnn = (double)nn;
    #pragma unroll
    for (int off = 16; off > 0; off >>= 1) {
        dnb += __shfl_xor_sync(0xffffffffu, dnb, off);
        dnn += __shfl_xor_sync(0xffffffffu, dnn, off);
    }
    if ((tid & 31) == 0) { snb[tid >> 5] = dnb; snn[tid >> 5] = dnn; }
    __syncthreads();

    if (tid == 0) {
        double noobj_sum = 0.0, n_noobj = 0.0;
        #pragma unroll
        for (int w = 0; w < TPB / 32; w++) { noobj_sum += snb[w]; n_noobj += snn[w]; }

        const Acc acc = g_acc;
        const double inv_nobj = 1.0 / acc.n_obj;
        const double noobj_loss = noobj_sum / n_noobj;
        const double obj_loss   = acc.obj_sum * inv_nobj;
        const double box_loss   = (acc.xy_sum + acc.wh_sum) * (0.5 * inv_nobj)
                                + acc.giou1m_sum * inv_nobj;
        const double class_loss = acc.cls_sum * inv_nobj;
        const double seg_loss   = acc.seg_sum / (acc.n_valid + 1e-9);

        const double box_l   = 8.0  * box_loss;
        const double obj_l   = 2.0  * obj_loss;
        const double noobj_l = 4.0  * noobj_loss;
        const double cls_l   = 1.0  * class_loss;
        const double seg_l   = 10.0 * seg_loss;

        out[0] = (float)box_l;
        out[1] = (float)obj_l;
        out[2] = (float)noobj_l;
        out[3] = (float)cls_l;
        out[4] = (float)seg_l;
        out[5] = (float)(box_l + obj_l + noobj_l + cls_l + seg_l);

        // reset accumulators for the next replay
        g_acc.obj_sum = 0.0; g_acc.giou1m_sum = 0.0; g_acc.xy_sum = 0.0;
        g_acc.wh_sum = 0.0;  g_acc.cls_sum = 0.0;    g_acc.seg_sum = 0.0;
        g_acc.n_obj = 0.0;   g_acc.n_valid = 0.0;
    }
}

extern "C" void kernel_launch(void* const* d_in, const int* in_sizes, int n_in,
                              void* d_out, int out_size)
{
    const float* preds   = (const float*)d_in[0];
    const float* target  = (const float*)d_in[1];
    const float* anchors = (const float*)d_in[2];
    const float* proto   = (const float*)d_in[3];
    const float* masks   = (const float*)d_in[4];
    float* out = (float*)d_out;

    cell_kernel<<<NCELL, TPB>>>(preds, target, anchors, proto, masks);
    finalize_kernel<<<1, TPB>>>(preds, target, out);
}

// round 7
// speedup vs baseline: 3.5775x; 1.3175x over previous
#include <cuda_runtime.h>
#include <math.h>

// Problem constants (fixed by setup_inputs)
#define N_  4
#define A_  3
#define S_  13
#define NC  80
#define NM  32
#define G_  16
#define H_  104
#define W_  104
#define PC  (5 + NC + NM)   // 117
#define HW  (H_ * W_)       // 10816
#define NCELL (N_ * A_ * S_ * S_)  // 2028
#define TPB 256
#define NOOBJ_BLKS 16

struct Acc {
    double obj_sum;
    double giou1m_sum;
    double xy_sum;
    double wh_sum;
    double cls_sum;
    double seg_sum;
    double n_obj;
    double n_valid;
    double noobj_sum;
    double n_noobj;
};

// Static-init zero; finalize_kernel resets after every use -> every replay
// (and the first correctness call) starts from zero. Deterministic.
__device__ Acc g_acc;

__device__ __forceinline__ float bce_logits(float x, float z) {
    return fmaxf(x, 0.0f) - x * z + log1pf(expf(-fabsf(x)));
}

__global__ void __launch_bounds__(TPB)
cell_kernel(const float* __restrict__ preds,
            const float* __restrict__ target,
            const float* __restrict__ anchors,
            const float* __restrict__ proto,
            const float* __restrict__ masks)
{
    const int tid = threadIdx.x;

    // ================= noobj reduction blocks =================
    if (blockIdx.x >= NCELL) {
        const int rb = blockIdx.x - NCELL;         // 0..NOOBJ_BLKS-1
        float nb = 0.0f, nn = 0.0f;
        // cells striped across NOOBJ_BLKS*TPB = 4096 threads
        for (int c = rb * TPB + tid; c < NCELL; c += NOOBJ_BLKS * TPB) {
            const float conf_t = target[(size_t)c * 7 + 4];
            if (conf_t == 0.0f) {
                nb += bce_logits(preds[(size_t)c * PC + 4], 0.0f);
                nn += 1.0f;
            }
        }
        double dnb = (double)nb, dnn = (double)nn;
        #pragma unroll
        for (int off = 16; off > 0; off >>= 1) {
            dnb += __shfl_xor_sync(0xffffffffu, dnb, off);
            dnn += __shfl_xor_sync(0xffffffffu, dnn, off);
        }
        __shared__ double snb[TPB / 32], snn[TPB / 32];
        if ((tid & 31) == 0) { snb[tid >> 5] = dnb; snn[tid >> 5] = dnn; }
        __syncthreads();
        if (tid == 0) {
            double tb = 0.0, tn = 0.0;
            #pragma unroll
            for (int w = 0; w < TPB / 32; w++) { tb += snb[w]; tn += snn[w]; }
            atomicAdd(&g_acc.noobj_sum, tb);
            atomicAdd(&g_acc.n_noobj, tn);
        }
        return;
    }

    // ================= obj cell blocks =================
    const int c = blockIdx.x;
    const float* t = target + (size_t)c * 7;
    const float* p = preds  + (size_t)c * PC;

    // obj check: uniform broadcast load; non-obj blocks exit immediately
    if (t[4] != 1.0f) return;

    __shared__ float tc[NM];
    __shared__ float sred[TPB / 32];
    __shared__ float s_cls;
    __shared__ int   sh_y1, sh_ny, sh_x1, sh_nx, sh_area, sh_id;

    // decode (n, a, i, j)
    const int n   = c / (A_ * S_ * S_);
    const int rem = c % (A_ * S_ * S_);
    const int a   = rem / (S_ * S_);
    const int ij  = rem % (S_ * S_);
    const int i   = ij / S_;
    const int j   = ij % S_;

    float v_obj = 0.f, v_giou1m = 0.f, v_xy = 0.f, v_wh = 0.f;

    // ---- warp 0 lane 0: box / giou / obj / xy / wh + region bounds ----
    if (tid == 0) {
        const float anw = anchors[a * 2 + 0];
        const float anh = anchors[a * 2 + 1];

        const float sx = 1.0f / (1.0f + expf(-p[0]));
        const float sy = 1.0f / (1.0f + expf(-p[1]));
        const float pw = expf(p[2]) * anw;
        const float ph = expf(p[3]) * anh;

        const float tx = t[0], ty = t[1], tw = t[2], th = t[3];

        const float eps = 1e-9f;
        const float b1x1 = sx - pw * 0.5f, b1y1 = sy - ph * 0.5f;
        const float b1x2 = sx + pw * 0.5f, b1y2 = sy + ph * 0.5f;
        const float b2x1 = tx - tw * 0.5f, b2y1 = ty - th * 0.5f;
        const float b2x2 = tx + tw * 0.5f, b2y2 = ty + th * 0.5f;
        const float a1 = fmaxf(b1x2 - b1x1, 0.0f) * fmaxf(b1y2 - b1y1, 0.0f) + eps;
        const float a2 = fmaxf(b2x2 - b2x1, 0.0f) * fmaxf(b2y2 - b2y1, 0.0f) + eps;
        const float iw = fmaxf(fminf(b1x2, b2x2) - fmaxf(b1x1, b2x1), 0.0f);
        const float ih = fmaxf(fminf(b1y2, b2y2) - fmaxf(b1y1, b2y1), 0.0f);
        const float inter = iw * ih + eps;
        const float uni   = a1 + a2 - inter + eps;
        const float iou   = inter / uni;
        const float cwd = fmaxf(b1x2, b2x2) - fminf(b1x1, b2x1);
        const float chd = fmaxf(b1y2, b2y2) - fminf(b1y1, b2y1);
        const float carea = cwd * chd + eps;
        const float giou  = iou - (carea - uni) / carea;

        v_giou1m = 1.0f - giou;
        v_obj    = bce_logits(p[4], fmaxf(giou, 0.0f));     // conf_t == 1
        v_xy     = bce_logits(sx, tx) + bce_logits(sy, ty);
        const float dw = p[2] - logf(1e-16f + tw / anw);
        const float dh = p[3] - logf(1e-16f + th / anh);
        v_wh     = dw * dw + dh * dh;

        // segment region bounds
        const float bx = (tx + (float)j) * ((float)W_ / (float)S_);
        const float by = (ty + (float)i) * ((float)H_ / (float)S_);
        const float bw = tw * ((float)W_ / (float)S_);
        const float bh = th * ((float)H_ / (float)S_);
        const int x1 = (int)floorf(bx - bw * 0.5f);
        const int x2 = (int)floorf(bx + bw * 0.5f);
        const int y1 = (int)floorf(by - bh * 0.5f);
        const int y2 = (int)floorf(by + bh * 0.5f);
        const int yl = max(y1, 0), yh = min(y2, H_);
        const int xl = max(x1, 0), xh = min(x2, W_);
        const int nrows = max(0, yh - yl);
        const int ncols = max(0, xh - xl);
        sh_y1 = yl; sh_ny = nrows;
        sh_x1 = xl; sh_nx = ncols;
        sh_area = nrows * ncols;
        int id = (int)t[6];
        sh_id = min(max(id, 0), G_ - 1);
    }

    // ---- warp 1: class log-softmax (shuffle-parallel over 80) ----
    if (tid >= 32 && tid < 64) {
        const int lane = tid - 32;
        float m = -3.4e38f;
        for (int k = lane; k < NC; k += 32) m = fmaxf(m, p[5 + k]);
        #pragma unroll
        for (int off = 16; off > 0; off >>= 1)
            m = fmaxf(m, __shfl_xor_sync(0xffffffffu, m, off));
        float se = 0.0f;
        for (int k = lane; k < NC; k += 32) se += expf(p[5 + k] - m);
        #pragma unroll
        for (int off = 16; off > 0; off >>= 1)
            se += __shfl_xor_sync(0xffffffffu, se, off);
        if (lane == 0) {
            const int lab = (int)t[5];
            s_cls = -(p[5 + lab] - m - logf(se));
        }
    }

    // ---- warp 2: tanh of the 32 mask coefficients ----
    if (tid >= 64 && tid < 96) tc[tid - 64] = tanhf(p[5 + NC + (tid - 64)]);

    __syncthreads();

    // ---- segment region sweep (all 256 threads) ----
    const int area = sh_area;
    float acc = 0.0f;
    if (area > 0) {
        const float* __restrict__ pr = proto + (size_t)n * NM * HW;
        const float* __restrict__ tm = masks + ((size_t)n * G_ + sh_id) * HW;
        const int npix = area;
        const int nx   = sh_nx;
        for (int pix = tid; pix < npix; pix += TPB) {
            const int r  = pix / nx;
            const int cc = pix - r * nx;
            const int off = (sh_y1 + r) * W_ + (sh_x1 + cc);
            float dot = 0.0f;
            #pragma unroll
            for (int m = 0; m < NM; m++)
                dot = fmaf(tc[m], pr[m * HW + off], dot);
            acc += bce_logits(dot, tm[off]);
        }
    }
    // warp reduce then cross-warp reduce
    #pragma unroll
    for (int off = 16; off > 0; off >>= 1)
        acc += __shfl_xor_sync(0xffffffffu, acc, off);
    if ((tid & 31) == 0) sred[tid >> 5] = acc;
    __syncthreads();
    if (tid == 0) {
        float rs = 0.0f;
        #pragma unroll
        for (int w = 0; w < TPB / 32; w++) rs += sred[w];

        atomicAdd(&g_acc.n_obj, 1.0);
        atomicAdd(&g_acc.giou1m_sum, (double)v_giou1m);
        atomicAdd(&g_acc.obj_sum, (double)v_obj);
        atomicAdd(&g_acc.xy_sum, (double)v_xy);
        atomicAdd(&g_acc.wh_sum, (double)v_wh);
        atomicAdd(&g_acc.cls_sum, (double)s_cls);
        if (area > 0) {
            atomicAdd(&g_acc.seg_sum, (double)(rs / (float)area));
            atomicAdd(&g_acc.n_valid, 1.0);
        }
    }
}

__global__ void finalize_kernel(float* __restrict__ out)
{
    if (threadIdx.x != 0) return;
    const Acc acc = g_acc;
    const double inv_nobj = 1.0 / acc.n_obj;
    const double noobj_loss = acc.noobj_sum / acc.n_noobj;
    const double obj_loss   = acc.obj_sum * inv_nobj;
    const double box_loss   = (acc.xy_sum + acc.wh_sum) * (0.5 * inv_nobj)
                            + acc.giou1m_sum * inv_nobj;
    const double class_loss = acc.cls_sum * inv_nobj;
    const double seg_loss   = acc.seg_sum / (acc.n_valid + 1e-9);

    const double box_l   = 8.0  * box_loss;
    const double obj_l   = 2.0  * obj_loss;
    const double noobj_l = 4.0  * noobj_loss;
    const double cls_l   = 1.0  * class_loss;
    const double seg_l   = 10.0 * seg_loss;

    out[0] = (float)box_l;
    out[1] = (float)obj_l;
    out[2] = (float)noobj_l;
    out[3] = (float)cls_l;
    out[4] = (float)seg_l;
    out[5] = (float)(box_l + obj_l + noobj_l + cls_l + seg_l);

    // reset accumulators for the next replay
    g_acc.obj_sum = 0.0; g_acc.giou1m_sum = 0.0; g_acc.xy_sum = 0.0;
    g_acc.wh_sum = 0.0;  g_acc.cls_sum = 0.0;    g_acc.seg_sum = 0.0;
    g_acc.n_obj = 0.0;   g_acc.n_valid = 0.0;
    g_acc.noobj_sum = 0.0; g_acc.n_noobj = 0.0;
}

extern "C" void kernel_launch(void* const* d_in, const int* in_sizes, int n_in,
                              void* d_out, int out_size)
{
    const float* preds   = (const float*)d_in[0];
    const float* target  = (const float*)d_in[1];
    const float* anchors = (const float*)d_in[2];
    const float* proto   = (const float*)d_in[3];
    const float* masks   = (const float*)d_in[4];
    float* out = (float*)d_out;

    cell_kernel<<<NCELL + NOOBJ_BLKS, TPB>>>(preds, target, anchors, proto, masks);
    finalize_kernel<<<1, 32>>>(out);
}